// round 1
// baseline (speedup 1.0000x reference)
#include <cuda_runtime.h>
#include <math.h>

#define MTOT 8192      // n * T = 4 * 2048
#define DIM 1024
#define FFD 4096
#define TT 2048
#define NBATCH 4
#define NHEAD 16
#define HDIM 64

// ---------------- scratch (no allocs allowed) ----------------
__device__ float g_X [MTOT * DIM];   // concat(kq, v)
__device__ float g_K [MTOT * DIM];
__device__ float g_Q [MTOT * DIM];
__device__ float g_V [MTOT * DIM];
__device__ float g_AO[MTOT * DIM];   // attention output
__device__ float g_H [MTOT * DIM];   // after LN1
__device__ float g_G [MTOT * FFD];   // gelu(h W1^T + b1)
__device__ float g_F [MTOT * DIM];   // ffn output

// ---------------- concat ----------------
__global__ void concat_kernel(const float* __restrict__ kq, const float* __restrict__ v) {
    int i = blockIdx.x * blockDim.x + threadIdx.x;   // over MTOT*DIM
    int m = i >> 10;
    int j = i & 1023;
    g_X[i] = (j < 512) ? kq[m * 512 + j] : v[m * 512 + (j - 512)];
}

// ---------------- GEMM: C[M,N] = A[M,K] * B[N,K]^T + bias, optional exact GELU ----
// 128x128 block, 256 threads, 8x8 microtile, K-tile = 8, register prefetch.
template<int GELU>
__global__ void __launch_bounds__(256) gemm_tn(
    const float* __restrict__ A, const float* __restrict__ B,
    const float* __restrict__ bias, float* __restrict__ C,
    int N, int K)
{
    __shared__ float As[8][128];
    __shared__ float Bs[8][128];

    const int bm = blockIdx.y * 128;
    const int bn = blockIdx.x * 128;
    const int tid = threadIdx.x;
    const int tx = tid & 15;       // 0..15 (col groups)
    const int ty = tid >> 4;       // 0..15 (row groups)
    const int lr = tid >> 1;       // 0..127 tile row for loading
    const int lk = (tid & 1) * 4;  // 0 or 4

    const float* Ag = A + (size_t)(bm + lr) * K + lk;
    const float* Bg = B + (size_t)(bn + lr) * K + lk;

    float acc[8][8];
#pragma unroll
    for (int i = 0; i < 8; i++)
#pragma unroll
        for (int j = 0; j < 8; j++) acc[i][j] = 0.f;

    float4 a4 = *(const float4*)(Ag);
    float4 b4 = *(const float4*)(Bg);

    for (int k0 = 0; k0 < K; k0 += 8) {
        As[lk + 0][lr] = a4.x; As[lk + 1][lr] = a4.y;
        As[lk + 2][lr] = a4.z; As[lk + 3][lr] = a4.w;
        Bs[lk + 0][lr] = b4.x; Bs[lk + 1][lr] = b4.y;
        Bs[lk + 2][lr] = b4.z; Bs[lk + 3][lr] = b4.w;
        __syncthreads();

        if (k0 + 8 < K) {                       // prefetch next tile
            a4 = *(const float4*)(Ag + k0 + 8);
            b4 = *(const float4*)(Bg + k0 + 8);
        }

#pragma unroll
        for (int k = 0; k < 8; k++) {
            float a[8], b[8];
            *(float4*)&a[0] = *(const float4*)&As[k][ty * 8];
            *(float4*)&a[4] = *(const float4*)&As[k][ty * 8 + 4];
            *(float4*)&b[0] = *(const float4*)&Bs[k][tx * 8];
            *(float4*)&b[4] = *(const float4*)&Bs[k][tx * 8 + 4];
#pragma unroll
            for (int i = 0; i < 8; i++)
#pragma unroll
                for (int j = 0; j < 8; j++)
                    acc[i][j] = fmaf(a[i], b[j], acc[i][j]);
        }
        __syncthreads();
    }

#pragma unroll
    for (int j = 0; j < 8; j++) {
        float bj = bias[bn + tx * 8 + j];
#pragma unroll
        for (int i = 0; i < 8; i++) {
            float v = acc[i][j] + bj;
            if (GELU) v = 0.5f * v * (1.f + erff(v * 0.7071067811865476f));
            C[(size_t)(bm + ty * 8 + i) * N + (bn + tx * 8 + j)] = v;
        }
    }
}

// ---------------- attention (flash style, causal, no scale) ----------------
// One block per (q-tile of 64, head, batch). 256 threads.
// Thread t handles query row r = t>>2, output/score columns c = (t&3) + 4*cc.
#define SPAD 65
#define SMEM_ATTN (4 * 64 * SPAD * 4)

__global__ void __launch_bounds__(256) attn_kernel(
    const float* __restrict__ Qg, const float* __restrict__ Kg,
    const float* __restrict__ Vg, float* __restrict__ AO)
{
    extern __shared__ float sm[];
    float* Qs = sm;
    float* Ks = sm + 64 * SPAD;
    float* Vs = sm + 2 * 64 * SPAD;
    float* Ps = sm + 3 * 64 * SPAD;

    const int qb = blockIdx.x;     // 0..31
    const int h  = blockIdx.y;
    const int b  = blockIdx.z;
    const int tid = threadIdx.x;
    const int r  = tid >> 2;       // query row within tile
    const int cg = tid & 3;        // column group (stride-4 columns)

    const size_t base = ((size_t)b * TT) * DIM + (size_t)h * HDIM;
    const int q0 = qb * 64;

    // load Q tile [64 x 64]
    for (int i = tid; i < 64 * 16; i += 256) {
        int row = i >> 4, c4 = i & 15;
        float4 qv = *(const float4*)(Qg + base + (size_t)(q0 + row) * DIM + c4 * 4);
        float* dst = &Qs[row * SPAD + c4 * 4];
        dst[0] = qv.x; dst[1] = qv.y; dst[2] = qv.z; dst[3] = qv.w;
    }

    float m = -INFINITY, l = 0.f;
    float O[16];
#pragma unroll
    for (int j = 0; j < 16; j++) O[j] = 0.f;

    const int qi = q0 + r;

    for (int jb = 0; jb <= qb; jb++) {
        __syncthreads();               // prev-iter smem reads done (also covers Q store)
        const int k0 = jb * 64;
        for (int i = tid; i < 64 * 16; i += 256) {
            int row = i >> 4, c4 = i & 15;
            size_t off = base + (size_t)(k0 + row) * DIM + c4 * 4;
            float4 kv = *(const float4*)(Kg + off);
            float4 vv = *(const float4*)(Vg + off);
            float* kd = &Ks[row * SPAD + c4 * 4];
            float* vd = &Vs[row * SPAD + c4 * 4];
            kd[0] = kv.x; kd[1] = kv.y; kd[2] = kv.z; kd[3] = kv.w;
            vd[0] = vv.x; vd[1] = vv.y; vd[2] = vv.z; vd[3] = vv.w;
        }
        __syncthreads();

        // scores for this thread's 16 columns
        float s[16];
#pragma unroll
        for (int cc = 0; cc < 16; cc++) s[cc] = 0.f;
        for (int d = 0; d < 64; d++) {
            float q = Qs[r * SPAD + d];
#pragma unroll
            for (int cc = 0; cc < 16; cc++) {
                int c = cg + cc * 4;
                s[cc] = fmaf(q, Ks[c * SPAD + d], s[cc]);
            }
        }
#pragma unroll
        for (int cc = 0; cc < 16; cc++) {
            int c = cg + cc * 4;
            if (k0 + c > qi) s[cc] = -INFINITY;
        }

        float mx = s[0];
#pragma unroll
        for (int cc = 1; cc < 16; cc++) mx = fmaxf(mx, s[cc]);
        mx = fmaxf(mx, __shfl_xor_sync(0xffffffffu, mx, 1));
        mx = fmaxf(mx, __shfl_xor_sync(0xffffffffu, mx, 2));

        float mnew = fmaxf(m, mx);
        float alpha = expf(m - mnew);   // 0 on first block (m = -inf)
        float ls = 0.f;
#pragma unroll
        for (int cc = 0; cc < 16; cc++) {
            float p = expf(s[cc] - mnew);
            Ps[r * SPAD + cg + cc * 4] = p;
            ls += p;
        }
        ls += __shfl_xor_sync(0xffffffffu, ls, 1);
        ls += __shfl_xor_sync(0xffffffffu, ls, 2);
        l = l * alpha + ls;
        m = mnew;
        __syncthreads();               // Ps visible

        // O = O*alpha + P @ V  (this thread: row r, dims cg+4*j)
#pragma unroll
        for (int j = 0; j < 16; j++) O[j] *= alpha;
        for (int c = 0; c < 64; c++) {
            float p = Ps[r * SPAD + c];
#pragma unroll
            for (int j = 0; j < 16; j++)
                O[j] = fmaf(p, Vs[c * SPAD + cg + j * 4], O[j]);
        }
    }

    float inv = 1.f / l;
    const size_t orow = base + (size_t)(q0 + r) * DIM;
#pragma unroll
    for (int j = 0; j < 16; j++)
        AO[orow + cg + j * 4] = O[j] * inv;
}

// ---------------- fused add + LayerNorm (row = 1024) ----------------
__global__ void __launch_bounds__(256) add_ln_kernel(
    const float* __restrict__ A, const float* __restrict__ B,
    const float* __restrict__ g, const float* __restrict__ beta,
    float* __restrict__ out)
{
    const int row = blockIdx.x;
    const float* a = A + (size_t)row * DIM;
    const float* b = B + (size_t)row * DIM;
    const int tid = threadIdx.x;

    float x[4];
    float s = 0.f, s2 = 0.f;
#pragma unroll
    for (int i = 0; i < 4; i++) {
        int c = tid + i * 256;
        x[i] = a[c] + b[c];
        s += x[i];
        s2 += x[i] * x[i];
    }
#pragma unroll
    for (int off = 16; off; off >>= 1) {
        s  += __shfl_down_sync(0xffffffffu, s,  off);
        s2 += __shfl_down_sync(0xffffffffu, s2, off);
    }
    __shared__ float ss[8], ss2[8];
    __shared__ float s_mean, s_inv;
    int w = tid >> 5;
    if ((tid & 31) == 0) { ss[w] = s; ss2[w] = s2; }
    __syncthreads();
    if (tid == 0) {
        float S = 0.f, S2 = 0.f;
#pragma unroll
        for (int i = 0; i < 8; i++) { S += ss[i]; S2 += ss2[i]; }
        float mu = S * (1.f / DIM);
        float var = S2 * (1.f / DIM) - mu * mu;
        s_mean = mu;
        s_inv = rsqrtf(var + 1e-5f);
    }
    __syncthreads();
    float mu = s_mean, iv = s_inv;
#pragma unroll
    for (int i = 0; i < 4; i++) {
        int c = tid + i * 256;
        out[(size_t)row * DIM + c] = (x[i] - mu) * iv * g[c] + beta[c];
    }
}

// ---------------- host ----------------
extern "C" void kernel_launch(void* const* d_in, const int* in_sizes, int n_in,
                              void* d_out, int out_size)
{
    const float* kq  = (const float*)d_in[0];
    const float* v   = (const float*)d_in[1];
    const float* Wk  = (const float*)d_in[2];
    const float* bk  = (const float*)d_in[3];
    const float* Wq  = (const float*)d_in[4];
    const float* bq  = (const float*)d_in[5];
    const float* Wv  = (const float*)d_in[6];
    const float* bv  = (const float*)d_in[7];
    const float* W1  = (const float*)d_in[8];
    const float* b1  = (const float*)d_in[9];
    const float* W2  = (const float*)d_in[10];
    const float* b2  = (const float*)d_in[11];
    const float* g1  = (const float*)d_in[12];
    const float* be1 = (const float*)d_in[13];
    const float* g2  = (const float*)d_in[14];
    const float* be2 = (const float*)d_in[15];
    float* out = (float*)d_out;

    float *X, *Kb, *Qb, *Vb, *AO, *Hh, *G, *F;
    cudaGetSymbolAddress((void**)&X,  g_X);
    cudaGetSymbolAddress((void**)&Kb, g_K);
    cudaGetSymbolAddress((void**)&Qb, g_Q);
    cudaGetSymbolAddress((void**)&Vb, g_V);
    cudaGetSymbolAddress((void**)&AO, g_AO);
    cudaGetSymbolAddress((void**)&Hh, g_H);
    cudaGetSymbolAddress((void**)&G,  g_G);
    cudaGetSymbolAddress((void**)&F,  g_F);

    concat_kernel<<<(MTOT * DIM) / 256, 256>>>(kq, v);

    dim3 gqkv(DIM / 128, MTOT / 128);
    gemm_tn<0><<<gqkv, 256>>>(X, Wk, bk, Kb, DIM, DIM);
    gemm_tn<0><<<gqkv, 256>>>(X, Wq, bq, Qb, DIM, DIM);
    gemm_tn<0><<<gqkv, 256>>>(X, Wv, bv, Vb, DIM, DIM);

    cudaFuncSetAttribute(attn_kernel, cudaFuncAttributeMaxDynamicSharedMemorySize, SMEM_ATTN);
    attn_kernel<<<dim3(TT / 64, NHEAD, NBATCH), 256, SMEM_ATTN>>>(Qb, Kb, Vb, AO);

    add_ln_kernel<<<MTOT, 256>>>(Vb, AO, g1, be1, Hh);

    gemm_tn<1><<<dim3(FFD / 128, MTOT / 128), 256>>>(Hh, W1, b1, G, FFD, DIM);
    gemm_tn<0><<<dim3(DIM / 128, MTOT / 128), 256>>>(G, W2, b2, F, DIM, FFD);

    add_ln_kernel<<<MTOT, 256>>>(Hh, F, g2, be2, out);
}

// round 2
// speedup vs baseline: 1.2875x; 1.2875x over previous
#include <cuda_runtime.h>
#include <math.h>

#define MTOT 8192      // n * T = 4 * 2048
#define DIM 1024
#define FFD 4096
#define TT 2048
#define NBATCH 4
#define NHEAD 16
#define HDIM 64

// ---------------- scratch (no allocs allowed) ----------------
__device__ float g_X [MTOT * DIM];   // concat(kq, v)
__device__ float g_K [MTOT * DIM];
__device__ float g_Q [MTOT * DIM];
__device__ float g_V [MTOT * DIM];
__device__ float g_AO[MTOT * DIM];   // attention output
__device__ float g_H [MTOT * DIM];   // after LN1
__device__ float g_G [MTOT * FFD];   // gelu(h W1^T + b1)
__device__ float g_F [MTOT * DIM];   // ffn output

// ---------------- concat ----------------
__global__ void concat_kernel(const float* __restrict__ kq, const float* __restrict__ v) {
    int i = blockIdx.x * blockDim.x + threadIdx.x;   // over MTOT*DIM
    int m = i >> 10;
    int j = i & 1023;
    g_X[i] = (j < 512) ? kq[m * 512 + j] : v[m * 512 + (j - 512)];
}

// ---------------- tf32 tensor-core GEMM ----------------
// C[M,N] = A[M,K] * B[N,K]^T + bias, optional exact GELU.
// 128x128x16 block tile, 8 warps (2x4), warp tile 64x32, mma.m16n8k8.tf32.
__device__ __forceinline__ unsigned cvt_tf32(float f) {
    unsigned r;
    asm("cvt.rna.tf32.f32 %0, %1;" : "=r"(r) : "f"(f));
    return r;
}

__device__ __forceinline__ void mma8(float* c, const unsigned* a, const unsigned* b) {
    asm volatile(
        "mma.sync.aligned.m16n8k8.row.col.f32.tf32.tf32.f32 "
        "{%0,%1,%2,%3}, {%4,%5,%6,%7}, {%8,%9}, {%0,%1,%2,%3};\n"
        : "+f"(c[0]), "+f"(c[1]), "+f"(c[2]), "+f"(c[3])
        : "r"(a[0]), "r"(a[1]), "r"(a[2]), "r"(a[3]), "r"(b[0]), "r"(b[1]));
}

#define SST 132   // smem row stride (conflict-free for frag loads & stores)

template<int GELU>
__global__ void __launch_bounds__(256) gemm_mma(
    const float* __restrict__ A, const float* __restrict__ B,
    const float* __restrict__ bias, float* __restrict__ C,
    int N, int K)
{
    __shared__ float As[2][16][SST];
    __shared__ float Bs[2][16][SST];

    const int tid  = threadIdx.x;
    const int lane = tid & 31;
    const int warp = tid >> 5;
    const int wm   = (warp & 1) * 64;   // warp tile M offset
    const int wn   = (warp >> 1) * 32;  // warp tile N offset
    const int g    = lane >> 2;         // group id 0..7
    const int tg   = lane & 3;          // thread-in-group 0..3
    const int bm   = blockIdx.y * 128;
    const int bn   = blockIdx.x * 128;

    // loader mapping: 128 rows x 2 k-halves (8 floats each)
    const int lm = tid & 127;
    const int lk = (tid >> 7) * 8;
    const float* Ap = A + (size_t)(bm + lm) * K + lk;
    const float* Bp = B + (size_t)(bn + lm) * K + lk;

    float acc[4][4][4];
#pragma unroll
    for (int i = 0; i < 4; i++)
#pragma unroll
        for (int j = 0; j < 4; j++)
#pragma unroll
            for (int q = 0; q < 4; q++) acc[i][j][q] = 0.f;

    float4 ra0 = *(const float4*)(Ap);
    float4 ra1 = *(const float4*)(Ap + 4);
    float4 rb0 = *(const float4*)(Bp);
    float4 rb1 = *(const float4*)(Bp + 4);

    int buf = 0;
    for (int k0 = 0; k0 < K; k0 += 16, buf ^= 1) {
        // store staged registers (converted to tf32) into smem, K-major
        As[buf][lk + 0][lm] = __uint_as_float(cvt_tf32(ra0.x));
        As[buf][lk + 1][lm] = __uint_as_float(cvt_tf32(ra0.y));
        As[buf][lk + 2][lm] = __uint_as_float(cvt_tf32(ra0.z));
        As[buf][lk + 3][lm] = __uint_as_float(cvt_tf32(ra0.w));
        As[buf][lk + 4][lm] = __uint_as_float(cvt_tf32(ra1.x));
        As[buf][lk + 5][lm] = __uint_as_float(cvt_tf32(ra1.y));
        As[buf][lk + 6][lm] = __uint_as_float(cvt_tf32(ra1.z));
        As[buf][lk + 7][lm] = __uint_as_float(cvt_tf32(ra1.w));
        Bs[buf][lk + 0][lm] = __uint_as_float(cvt_tf32(rb0.x));
        Bs[buf][lk + 1][lm] = __uint_as_float(cvt_tf32(rb0.y));
        Bs[buf][lk + 2][lm] = __uint_as_float(cvt_tf32(rb0.z));
        Bs[buf][lk + 3][lm] = __uint_as_float(cvt_tf32(rb0.w));
        Bs[buf][lk + 4][lm] = __uint_as_float(cvt_tf32(rb1.x));
        Bs[buf][lk + 5][lm] = __uint_as_float(cvt_tf32(rb1.y));
        Bs[buf][lk + 6][lm] = __uint_as_float(cvt_tf32(rb1.z));
        Bs[buf][lk + 7][lm] = __uint_as_float(cvt_tf32(rb1.w));
        __syncthreads();

        if (k0 + 16 < K) {       // prefetch next K-chunk into registers
            ra0 = *(const float4*)(Ap + k0 + 16);
            ra1 = *(const float4*)(Ap + k0 + 20);
            rb0 = *(const float4*)(Bp + k0 + 16);
            rb1 = *(const float4*)(Bp + k0 + 20);
        }

#pragma unroll
        for (int ks = 0; ks < 16; ks += 8) {
            unsigned af[4][4], bf[4][2];
#pragma unroll
            for (int mi = 0; mi < 4; mi++) {
                int m0 = wm + mi * 16;
                af[mi][0] = __float_as_uint(As[buf][ks + tg    ][m0 + g]);
                af[mi][1] = __float_as_uint(As[buf][ks + tg    ][m0 + g + 8]);
                af[mi][2] = __float_as_uint(As[buf][ks + tg + 4][m0 + g]);
                af[mi][3] = __float_as_uint(As[buf][ks + tg + 4][m0 + g + 8]);
            }
#pragma unroll
            for (int ni = 0; ni < 4; ni++) {
                int n0 = wn + ni * 8;
                bf[ni][0] = __float_as_uint(Bs[buf][ks + tg    ][n0 + g]);
                bf[ni][1] = __float_as_uint(Bs[buf][ks + tg + 4][n0 + g]);
            }
#pragma unroll
            for (int mi = 0; mi < 4; mi++)
#pragma unroll
                for (int ni = 0; ni < 4; ni++)
                    mma8(acc[mi][ni], af[mi], bf[ni]);
        }
        __syncthreads();
    }

    // epilogue
#pragma unroll
    for (int ni = 0; ni < 4; ni++) {
        int n = bn + wn + ni * 8 + tg * 2;
        float b0 = bias[n], b1 = bias[n + 1];
#pragma unroll
        for (int mi = 0; mi < 4; mi++) {
            int m = bm + wm + mi * 16 + g;
            float v00 = acc[mi][ni][0] + b0;
            float v01 = acc[mi][ni][1] + b1;
            float v10 = acc[mi][ni][2] + b0;
            float v11 = acc[mi][ni][3] + b1;
            if (GELU) {
                v00 = 0.5f * v00 * (1.f + erff(v00 * 0.7071067811865476f));
                v01 = 0.5f * v01 * (1.f + erff(v01 * 0.7071067811865476f));
                v10 = 0.5f * v10 * (1.f + erff(v10 * 0.7071067811865476f));
                v11 = 0.5f * v11 * (1.f + erff(v11 * 0.7071067811865476f));
            }
            float2 lo = make_float2(v00, v01);
            float2 hi = make_float2(v10, v11);
            *(float2*)&C[(size_t)m * N + n] = lo;
            *(float2*)&C[(size_t)(m + 8) * N + n] = hi;
        }
    }
}

// ---------------- attention (flash style, causal, no scale) ----------------
#define SPAD 65
#define SMEM_ATTN (4 * 64 * SPAD * 4)

__global__ void __launch_bounds__(256) attn_kernel(
    const float* __restrict__ Qg, const float* __restrict__ Kg,
    const float* __restrict__ Vg, float* __restrict__ AO)
{
    extern __shared__ float sm[];
    float* Qs = sm;
    float* Ks = sm + 64 * SPAD;
    float* Vs = sm + 2 * 64 * SPAD;
    float* Ps = sm + 3 * 64 * SPAD;

    const int qb = blockIdx.x;
    const int h  = blockIdx.y;
    const int b  = blockIdx.z;
    const int tid = threadIdx.x;
    const int r  = tid >> 2;
    const int cg = tid & 3;

    const size_t base = ((size_t)b * TT) * DIM + (size_t)h * HDIM;
    const int q0 = qb * 64;

    for (int i = tid; i < 64 * 16; i += 256) {
        int row = i >> 4, c4 = i & 15;
        float4 qv = *(const float4*)(Qg + base + (size_t)(q0 + row) * DIM + c4 * 4);
        float* dst = &Qs[row * SPAD + c4 * 4];
        dst[0] = qv.x; dst[1] = qv.y; dst[2] = qv.z; dst[3] = qv.w;
    }

    float m = -INFINITY, l = 0.f;
    float O[16];
#pragma unroll
    for (int j = 0; j < 16; j++) O[j] = 0.f;

    const int qi = q0 + r;

    for (int jb = 0; jb <= qb; jb++) {
        __syncthreads();
        const int k0 = jb * 64;
        for (int i = tid; i < 64 * 16; i += 256) {
            int row = i >> 4, c4 = i & 15;
            size_t off = base + (size_t)(k0 + row) * DIM + c4 * 4;
            float4 kv = *(const float4*)(Kg + off);
            float4 vv = *(const float4*)(Vg + off);
            float* kd = &Ks[row * SPAD + c4 * 4];
            float* vd = &Vs[row * SPAD + c4 * 4];
            kd[0] = kv.x; kd[1] = kv.y; kd[2] = kv.z; kd[3] = kv.w;
            vd[0] = vv.x; vd[1] = vv.y; vd[2] = vv.z; vd[3] = vv.w;
        }
        __syncthreads();

        float s[16];
#pragma unroll
        for (int cc = 0; cc < 16; cc++) s[cc] = 0.f;
        for (int d = 0; d < 64; d++) {
            float q = Qs[r * SPAD + d];
#pragma unroll
            for (int cc = 0; cc < 16; cc++) {
                int c = cg + cc * 4;
                s[cc] = fmaf(q, Ks[c * SPAD + d], s[cc]);
            }
        }
#pragma unroll
        for (int cc = 0; cc < 16; cc++) {
            int c = cg + cc * 4;
            if (k0 + c > qi) s[cc] = -INFINITY;
        }

        float mx = s[0];
#pragma unroll
        for (int cc = 1; cc < 16; cc++) mx = fmaxf(mx, s[cc]);
        mx = fmaxf(mx, __shfl_xor_sync(0xffffffffu, mx, 1));
        mx = fmaxf(mx, __shfl_xor_sync(0xffffffffu, mx, 2));

        float mnew = fmaxf(m, mx);
        float alpha = expf(m - mnew);
        float ls = 0.f;
#pragma unroll
        for (int cc = 0; cc < 16; cc++) {
            float p = expf(s[cc] - mnew);
            Ps[r * SPAD + cg + cc * 4] = p;
            ls += p;
        }
        ls += __shfl_xor_sync(0xffffffffu, ls, 1);
        ls += __shfl_xor_sync(0xffffffffu, ls, 2);
        l = l * alpha + ls;
        m = mnew;
        __syncthreads();

#pragma unroll
        for (int j = 0; j < 16; j++) O[j] *= alpha;
        for (int c = 0; c < 64; c++) {
            float p = Ps[r * SPAD + c];
#pragma unroll
            for (int j = 0; j < 16; j++)
                O[j] = fmaf(p, Vs[c * SPAD + cg + j * 4], O[j]);
        }
    }

    float inv = 1.f / l;
    const size_t orow = base + (size_t)(q0 + r) * DIM;
#pragma unroll
    for (int j = 0; j < 16; j++)
        AO[orow + cg + j * 4] = O[j] * inv;
}

// ---------------- fused add + LayerNorm (row = 1024) ----------------
__global__ void __launch_bounds__(256) add_ln_kernel(
    const float* __restrict__ A, const float* __restrict__ B,
    const float* __restrict__ g, const float* __restrict__ beta,
    float* __restrict__ out)
{
    const int row = blockIdx.x;
    const float* a = A + (size_t)row * DIM;
    const float* b = B + (size_t)row * DIM;
    const int tid = threadIdx.x;

    float x[4];
    float s = 0.f, s2 = 0.f;
#pragma unroll
    for (int i = 0; i < 4; i++) {
        int c = tid + i * 256;
        x[i] = a[c] + b[c];
        s += x[i];
        s2 += x[i] * x[i];
    }
#pragma unroll
    for (int off = 16; off; off >>= 1) {
        s  += __shfl_down_sync(0xffffffffu, s,  off);
        s2 += __shfl_down_sync(0xffffffffu, s2, off);
    }
    __shared__ float ss[8], ss2[8];
    __shared__ float s_mean, s_inv;
    int w = tid >> 5;
    if ((tid & 31) == 0) { ss[w] = s; ss2[w] = s2; }
    __syncthreads();
    if (tid == 0) {
        float S = 0.f, S2 = 0.f;
#pragma unroll
        for (int i = 0; i < 8; i++) { S += ss[i]; S2 += ss2[i]; }
        float mu = S * (1.f / DIM);
        float var = S2 * (1.f / DIM) - mu * mu;
        s_mean = mu;
        s_inv = rsqrtf(var + 1e-5f);
    }
    __syncthreads();
    float mu = s_mean, iv = s_inv;
#pragma unroll
    for (int i = 0; i < 4; i++) {
        int c = tid + i * 256;
        out[(size_t)row * DIM + c] = (x[i] - mu) * iv * g[c] + beta[c];
    }
}

// ---------------- host ----------------
extern "C" void kernel_launch(void* const* d_in, const int* in_sizes, int n_in,
                              void* d_out, int out_size)
{
    const float* kq  = (const float*)d_in[0];
    const float* v   = (const float*)d_in[1];
    const float* Wk  = (const float*)d_in[2];
    const float* bk  = (const float*)d_in[3];
    const float* Wq  = (const float*)d_in[4];
    const float* bq  = (const float*)d_in[5];
    const float* Wv  = (const float*)d_in[6];
    const float* bv  = (const float*)d_in[7];
    const float* W1  = (const float*)d_in[8];
    const float* b1  = (const float*)d_in[9];
    const float* W2  = (const float*)d_in[10];
    const float* b2  = (const float*)d_in[11];
    const float* g1  = (const float*)d_in[12];
    const float* be1 = (const float*)d_in[13];
    const float* g2  = (const float*)d_in[14];
    const float* be2 = (const float*)d_in[15];
    float* out = (float*)d_out;

    float *X, *Kb, *Qb, *Vb, *AO, *Hh, *G, *F;
    cudaGetSymbolAddress((void**)&X,  g_X);
    cudaGetSymbolAddress((void**)&Kb, g_K);
    cudaGetSymbolAddress((void**)&Qb, g_Q);
    cudaGetSymbolAddress((void**)&Vb, g_V);
    cudaGetSymbolAddress((void**)&AO, g_AO);
    cudaGetSymbolAddress((void**)&Hh, g_H);
    cudaGetSymbolAddress((void**)&G,  g_G);
    cudaGetSymbolAddress((void**)&F,  g_F);

    concat_kernel<<<(MTOT * DIM) / 256, 256>>>(kq, v);

    dim3 gqkv(DIM / 128, MTOT / 128);
    gemm_mma<0><<<gqkv, 256>>>(X, Wk, bk, Kb, DIM, DIM);
    gemm_mma<0><<<gqkv, 256>>>(X, Wq, bq, Qb, DIM, DIM);
    gemm_mma<0><<<gqkv, 256>>>(X, Wv, bv, Vb, DIM, DIM);

    cudaFuncSetAttribute(attn_kernel, cudaFuncAttributeMaxDynamicSharedMemorySize, SMEM_ATTN);
    attn_kernel<<<dim3(TT / 64, NHEAD, NBATCH), 256, SMEM_ATTN>>>(Qb, Kb, Vb, AO);

    add_ln_kernel<<<MTOT, 256>>>(Vb, AO, g1, be1, Hh);

    gemm_mma<1><<<dim3(FFD / 128, MTOT / 128), 256>>>(Hh, W1, b1, G, FFD, DIM);
    gemm_mma<0><<<dim3(DIM / 128, MTOT / 128), 256>>>(G, W2, b2, F, DIM, FFD);

    add_ln_kernel<<<MTOT, 256>>>(Hh, F, g2, be2, out);
}

// round 3
// speedup vs baseline: 2.4229x; 1.8819x over previous
#include <cuda_runtime.h>
#include <math.h>

#define MTOT 8192      // n * T = 4 * 2048
#define DIM 1024
#define FFD 4096
#define TT 2048
#define NBATCH 4
#define NHEAD 16
#define HDIM 64

// ---------------- scratch (no allocs allowed) ----------------
__device__ float g_X [MTOT * DIM];   // concat(kq, v)
__device__ float g_K [MTOT * DIM];
__device__ float g_Q [MTOT * DIM];
__device__ float g_V [MTOT * DIM];
__device__ float g_AO[MTOT * DIM];   // attention output
__device__ float g_H [MTOT * DIM];   // after LN1
__device__ float g_G [MTOT * FFD];   // gelu(h W1^T + b1)
__device__ float g_F [MTOT * DIM];   // ffn output

// ---------------- helpers ----------------
__device__ __forceinline__ unsigned cvt_tf32(float f) {
    unsigned r;
    asm("cvt.rna.tf32.f32 %0, %1;" : "=r"(r) : "f"(f));
    return r;
}
__device__ __forceinline__ float tf32f(float f) { return __uint_as_float(cvt_tf32(f)); }

__device__ __forceinline__ void mma8(float* c, const unsigned* a, const unsigned* b) {
    asm volatile(
        "mma.sync.aligned.m16n8k8.row.col.f32.tf32.tf32.f32 "
        "{%0,%1,%2,%3}, {%4,%5,%6,%7}, {%8,%9}, {%0,%1,%2,%3};\n"
        : "+f"(c[0]), "+f"(c[1]), "+f"(c[2]), "+f"(c[3])
        : "r"(a[0]), "r"(a[1]), "r"(a[2]), "r"(a[3]), "r"(b[0]), "r"(b[1]));
}

// ---------------- concat ----------------
__global__ void concat_kernel(const float* __restrict__ kq, const float* __restrict__ v) {
    int i = blockIdx.x * blockDim.x + threadIdx.x;
    int m = i >> 10;
    int j = i & 1023;
    g_X[i] = (j < 512) ? kq[m * 512 + j] : v[m * 512 + (j - 512)];
}

// ---------------- tf32 tensor-core GEMM ----------------
// C[M,N] = A[M,K]*B[N,K]^T + bias (+GELU). 128x128x16 tile, 8 warps, 64x32 warp tile.
// Pair-interleaved smem: plane p of kstep ks holds (k=p, k=p+4) float2 pairs, row-indexed.
// Plane stride 132 float2 (264 floats, ==8 mod 32 banks): conflict-free LDS.64/STS.64.
template<int GELU>
__global__ void __launch_bounds__(256) gemm_mma(
    const float* __restrict__ A, const float* __restrict__ B,
    const float* __restrict__ bias, float* __restrict__ C,
    int N, int K)
{
    __shared__ float2 As2[2][8][132];
    __shared__ float2 Bs2[2][8][132];

    const int tid  = threadIdx.x;
    const int lane = tid & 31;
    const int warp = tid >> 5;
    const int wm   = (warp & 1) * 64;
    const int wn   = (warp >> 1) * 32;
    const int g    = lane >> 2;
    const int tg   = lane & 3;
    const int bm   = blockIdx.y * 128;
    const int bn   = blockIdx.x * 128;

    const int lm  = tid & 127;       // row this thread loads
    const int lks = tid >> 7;        // kstep (0/1) this thread loads
    const float* Ap = A + (size_t)(bm + lm) * K + lks * 8;
    const float* Bp = B + (size_t)(bn + lm) * K + lks * 8;

    float acc[4][4][4];
#pragma unroll
    for (int i = 0; i < 4; i++)
#pragma unroll
        for (int j = 0; j < 4; j++)
#pragma unroll
            for (int q = 0; q < 4; q++) acc[i][j][q] = 0.f;

    float ra[8], rb[8];
    {
        float4 a0 = *(const float4*)(Ap), a1 = *(const float4*)(Ap + 4);
        float4 b0 = *(const float4*)(Bp), b1 = *(const float4*)(Bp + 4);
        ra[0]=a0.x; ra[1]=a0.y; ra[2]=a0.z; ra[3]=a0.w; ra[4]=a1.x; ra[5]=a1.y; ra[6]=a1.z; ra[7]=a1.w;
        rb[0]=b0.x; rb[1]=b0.y; rb[2]=b0.z; rb[3]=b0.w; rb[4]=b1.x; rb[5]=b1.y; rb[6]=b1.z; rb[7]=b1.w;
    }
#pragma unroll
    for (int p = 0; p < 4; p++) {
        As2[0][lks * 4 + p][lm] = make_float2(tf32f(ra[p]), tf32f(ra[p + 4]));
        Bs2[0][lks * 4 + p][lm] = make_float2(tf32f(rb[p]), tf32f(rb[p + 4]));
    }
    __syncthreads();

    int buf = 0;
    for (int k0 = 0; k0 < K; k0 += 16) {
        const bool more = (k0 + 16 < K);
        if (more) {
            float4 a0 = *(const float4*)(Ap + k0 + 16), a1 = *(const float4*)(Ap + k0 + 20);
            float4 b0 = *(const float4*)(Bp + k0 + 16), b1 = *(const float4*)(Bp + k0 + 20);
            ra[0]=a0.x; ra[1]=a0.y; ra[2]=a0.z; ra[3]=a0.w; ra[4]=a1.x; ra[5]=a1.y; ra[6]=a1.z; ra[7]=a1.w;
            rb[0]=b0.x; rb[1]=b0.y; rb[2]=b0.z; rb[3]=b0.w; rb[4]=b1.x; rb[5]=b1.y; rb[6]=b1.z; rb[7]=b1.w;
        }

#pragma unroll
        for (int ks = 0; ks < 2; ks++) {
            unsigned af[4][4], bf[4][2];
#pragma unroll
            for (int mi = 0; mi < 4; mi++) {
                float2 lo = As2[buf][ks * 4 + tg][wm + mi * 16 + g];
                float2 hi = As2[buf][ks * 4 + tg][wm + mi * 16 + g + 8];
                af[mi][0] = __float_as_uint(lo.x);
                af[mi][1] = __float_as_uint(hi.x);
                af[mi][2] = __float_as_uint(lo.y);
                af[mi][3] = __float_as_uint(hi.y);
            }
#pragma unroll
            for (int ni = 0; ni < 4; ni++) {
                float2 bb = Bs2[buf][ks * 4 + tg][wn + ni * 8 + g];
                bf[ni][0] = __float_as_uint(bb.x);
                bf[ni][1] = __float_as_uint(bb.y);
            }
#pragma unroll
            for (int mi = 0; mi < 4; mi++)
#pragma unroll
                for (int ni = 0; ni < 4; ni++)
                    mma8(acc[mi][ni], af[mi], bf[ni]);
        }

        if (more) {
#pragma unroll
            for (int p = 0; p < 4; p++) {
                As2[buf ^ 1][lks * 4 + p][lm] = make_float2(tf32f(ra[p]), tf32f(ra[p + 4]));
                Bs2[buf ^ 1][lks * 4 + p][lm] = make_float2(tf32f(rb[p]), tf32f(rb[p + 4]));
            }
        }
        __syncthreads();
        buf ^= 1;
    }

    // epilogue
#pragma unroll
    for (int ni = 0; ni < 4; ni++) {
        int n = bn + wn + ni * 8 + tg * 2;
        float b0 = bias[n], b1 = bias[n + 1];
#pragma unroll
        for (int mi = 0; mi < 4; mi++) {
            int m = bm + wm + mi * 16 + g;
            float v00 = acc[mi][ni][0] + b0;
            float v01 = acc[mi][ni][1] + b1;
            float v10 = acc[mi][ni][2] + b0;
            float v11 = acc[mi][ni][3] + b1;
            if (GELU) {
                v00 = 0.5f * v00 * (1.f + erff(v00 * 0.7071067811865476f));
                v01 = 0.5f * v01 * (1.f + erff(v01 * 0.7071067811865476f));
                v10 = 0.5f * v10 * (1.f + erff(v10 * 0.7071067811865476f));
                v11 = 0.5f * v11 * (1.f + erff(v11 * 0.7071067811865476f));
            }
            *(float2*)&C[(size_t)m * N + n] = make_float2(v00, v01);
            *(float2*)&C[(size_t)(m + 8) * N + n] = make_float2(v10, v11);
        }
    }
}

// ---------------- attention: tf32 mma flash, causal, no scale ----------------
// Block: 128 threads (4 warps), 64 q-rows (16/warp), kv tiles of 64, d = 64.
// smem (floats): K planes [0,4352), V planes [4352,8704), QP region [8704,13312)
//   K planes: 32 planes (8 ksteps over d x 4 tg) of 68 float2 (pairs over d)
//   V planes: 32 planes (8 ksteps over kv x 4 tg) of 68 float2 (pairs over kv)
//   QP: first Q planes (same layout as K), then reused as P rows [64][72]
#define QPLN 68           // float2 per plane row (64 + 4 pad): 136 floats == 8 mod 32 banks
#define PSTR 72           // P row stride in floats (== 8 mod 32 banks)
#define SMEM_ATTN (13312 * 4)

__global__ void __launch_bounds__(128, 3) attn_mma(
    const float* __restrict__ Qg, const float* __restrict__ Kg,
    const float* __restrict__ Vg, float* __restrict__ AO)
{
    extern __shared__ float sm[];
    float2* Kp  = (float2*)sm;            // 32*68 float2
    float*  Vf  = sm + 4352;              // V planes as floats
    float2* Vp  = (float2*)Vf;
    float2* Qp2 = (float2*)(sm + 8704);   // Q planes
    float*  Ps  = sm + 8704;              // P rows (aliases Q planes; safe after frag load)

    const int qb = blockIdx.x, h = blockIdx.y, b = blockIdx.z;
    const int tid = threadIdx.x;
    const int warp = tid >> 5, lane = tid & 31;
    const int g = lane >> 2, tg = lane & 3;
    const int qw0 = warp * 16;
    const size_t base = ((size_t)b * TT) * DIM + (size_t)h * HDIM;
    const int q0 = qb * 64;

    // produce Q planes (pairs over d)
    for (int t = tid; t < 512; t += 128) {
        int row = t & 63, ks = t >> 6;
        const float* src = Qg + base + (size_t)(q0 + row) * DIM + ks * 8;
        float4 v0 = *(const float4*)src, v1 = *(const float4*)(src + 4);
        float a[8] = {v0.x, v0.y, v0.z, v0.w, v1.x, v1.y, v1.z, v1.w};
#pragma unroll
        for (int p = 0; p < 4; p++)
            Qp2[(ks * 4 + p) * QPLN + row] = make_float2(tf32f(a[p]), tf32f(a[p + 4]));
    }
    __syncthreads();

    // persistent Q fragments
    unsigned qf[8][4];
#pragma unroll
    for (int ks = 0; ks < 8; ks++) {
        float2 lo = Qp2[(ks * 4 + tg) * QPLN + qw0 + g];
        float2 hi = Qp2[(ks * 4 + tg) * QPLN + qw0 + g + 8];
        qf[ks][0] = __float_as_uint(lo.x);
        qf[ks][1] = __float_as_uint(hi.x);
        qf[ks][2] = __float_as_uint(lo.y);
        qf[ks][3] = __float_as_uint(hi.y);
    }

    float o[8][4];
#pragma unroll
    for (int ni = 0; ni < 8; ni++)
#pragma unroll
        for (int q = 0; q < 4; q++) o[ni][q] = 0.f;
    float m0 = -INFINITY, m1 = -INFINITY, l0 = 0.f, l1 = 0.f;

    for (int jb = 0; jb <= qb; jb++) {
        __syncthreads();   // all warps done with prior K/V/P (and Q frags on iter 0)
        const int k0 = jb * 64;
        // K planes: pairs over d
        for (int t = tid; t < 512; t += 128) {
            int row = t & 63, ks = t >> 6;
            const float* src = Kg + base + (size_t)(k0 + row) * DIM + ks * 8;
            float4 v0 = *(const float4*)src, v1 = *(const float4*)(src + 4);
            float a[8] = {v0.x, v0.y, v0.z, v0.w, v1.x, v1.y, v1.z, v1.w};
#pragma unroll
            for (int p = 0; p < 4; p++)
                Kp[(ks * 4 + p) * QPLN + row] = make_float2(tf32f(a[p]), tf32f(a[p + 4]));
        }
        // V planes: pairs over kv (scalar scatter)
        for (int t = tid; t < 512; t += 128) {
            int row = t & 63, ch = t >> 6;
            const float* src = Vg + base + (size_t)(k0 + row) * DIM + ch * 8;
            float4 v0 = *(const float4*)src, v1 = *(const float4*)(src + 4);
            float a[8] = {v0.x, v0.y, v0.z, v0.w, v1.x, v1.y, v1.z, v1.w};
            int plane = (row >> 3) * 4 + (row & 3);
            int slot = (row & 4) >> 2;
            float* dst = Vf + plane * 136 + slot;
#pragma unroll
            for (int e = 0; e < 8; e++)
                dst[(ch * 8 + e) * 2] = tf32f(a[e]);
        }
        __syncthreads();

        // S = Q K^T  (m=16 rows, n=64 kv, k=64 d)
        float s[8][4];
#pragma unroll
        for (int ni = 0; ni < 8; ni++)
#pragma unroll
            for (int q = 0; q < 4; q++) s[ni][q] = 0.f;
#pragma unroll
        for (int ks = 0; ks < 8; ks++) {
#pragma unroll
            for (int ni = 0; ni < 8; ni++) {
                float2 kb = Kp[(ks * 4 + tg) * QPLN + ni * 8 + g];
                unsigned bf[2] = {__float_as_uint(kb.x), __float_as_uint(kb.y)};
                mma8(s[ni], qf[ks], bf);
            }
        }

        // causal mask (only diagonal tile needs it)
        if (jb == qb) {
#pragma unroll
            for (int ni = 0; ni < 8; ni++) {
                int c = ni * 8 + 2 * tg;
                if (c     > qw0 + g)     s[ni][0] = -INFINITY;
                if (c + 1 > qw0 + g)     s[ni][1] = -INFINITY;
                if (c     > qw0 + g + 8) s[ni][2] = -INFINITY;
                if (c + 1 > qw0 + g + 8) s[ni][3] = -INFINITY;
            }
        }

        // online softmax (rows g and g+8)
        float rx0 = -INFINITY, rx1 = -INFINITY;
#pragma unroll
        for (int ni = 0; ni < 8; ni++) {
            rx0 = fmaxf(rx0, fmaxf(s[ni][0], s[ni][1]));
            rx1 = fmaxf(rx1, fmaxf(s[ni][2], s[ni][3]));
        }
        rx0 = fmaxf(rx0, __shfl_xor_sync(0xffffffffu, rx0, 1));
        rx0 = fmaxf(rx0, __shfl_xor_sync(0xffffffffu, rx0, 2));
        rx1 = fmaxf(rx1, __shfl_xor_sync(0xffffffffu, rx1, 1));
        rx1 = fmaxf(rx1, __shfl_xor_sync(0xffffffffu, rx1, 2));

        float mn0 = fmaxf(m0, rx0), mn1 = fmaxf(m1, rx1);
        float al0 = __expf(m0 - mn0), al1 = __expf(m1 - mn1);
        float ps0 = 0.f, ps1 = 0.f;
#pragma unroll
        for (int ni = 0; ni < 8; ni++) {
            float p0 = tf32f(__expf(s[ni][0] - mn0));
            float p1 = tf32f(__expf(s[ni][1] - mn0));
            float p2 = tf32f(__expf(s[ni][2] - mn1));
            float p3 = tf32f(__expf(s[ni][3] - mn1));
            s[ni][0] = p0; s[ni][1] = p1; s[ni][2] = p2; s[ni][3] = p3;
            ps0 += p0 + p1;
            ps1 += p2 + p3;
        }
        ps0 += __shfl_xor_sync(0xffffffffu, ps0, 1);
        ps0 += __shfl_xor_sync(0xffffffffu, ps0, 2);
        ps1 += __shfl_xor_sync(0xffffffffu, ps1, 1);
        ps1 += __shfl_xor_sync(0xffffffffu, ps1, 2);
        l0 = l0 * al0 + ps0;
        l1 = l1 * al1 + ps1;
        m0 = mn0; m1 = mn1;
#pragma unroll
        for (int ni = 0; ni < 8; ni++) {
            o[ni][0] *= al0; o[ni][1] *= al0;
            o[ni][2] *= al1; o[ni][3] *= al1;
        }

        // stage P to smem (per-warp rows; cross-lane reads need syncwarp only)
#pragma unroll
        for (int ni = 0; ni < 8; ni++) {
            *(float2*)&Ps[(qw0 + g)     * PSTR + ni * 8 + 2 * tg] = make_float2(s[ni][0], s[ni][1]);
            *(float2*)&Ps[(qw0 + g + 8) * PSTR + ni * 8 + 2 * tg] = make_float2(s[ni][2], s[ni][3]);
        }
        __syncwarp();

        // O += P V  (m=16 rows, n=64 d, k=64 kv)
#pragma unroll
        for (int ks = 0; ks < 8; ks++) {
            unsigned pf[4];
            pf[0] = __float_as_uint(Ps[(qw0 + g)     * PSTR + ks * 8 + tg]);
            pf[1] = __float_as_uint(Ps[(qw0 + g + 8) * PSTR + ks * 8 + tg]);
            pf[2] = __float_as_uint(Ps[(qw0 + g)     * PSTR + ks * 8 + tg + 4]);
            pf[3] = __float_as_uint(Ps[(qw0 + g + 8) * PSTR + ks * 8 + tg + 4]);
#pragma unroll
            for (int ni = 0; ni < 8; ni++) {
                float2 vb = Vp[(ks * 4 + tg) * QPLN + ni * 8 + g];
                unsigned bf[2] = {__float_as_uint(vb.x), __float_as_uint(vb.y)};
                mma8(o[ni], pf, bf);
            }
        }
    }

    float i0 = 1.f / l0, i1 = 1.f / l1;
#pragma unroll
    for (int ni = 0; ni < 8; ni++) {
        size_t r0 = base + (size_t)(q0 + qw0 + g) * DIM + ni * 8 + 2 * tg;
        size_t r1 = base + (size_t)(q0 + qw0 + g + 8) * DIM + ni * 8 + 2 * tg;
        *(float2*)&AO[r0] = make_float2(o[ni][0] * i0, o[ni][1] * i0);
        *(float2*)&AO[r1] = make_float2(o[ni][2] * i1, o[ni][3] * i1);
    }
}

// ---------------- fused add + LayerNorm (row = 1024) ----------------
__global__ void __launch_bounds__(256) add_ln_kernel(
    const float* __restrict__ A, const float* __restrict__ B,
    const float* __restrict__ g, const float* __restrict__ beta,
    float* __restrict__ out)
{
    const int row = blockIdx.x;
    const float* a = A + (size_t)row * DIM;
    const float* b = B + (size_t)row * DIM;
    const int tid = threadIdx.x;

    float x[4];
    float s = 0.f, s2 = 0.f;
#pragma unroll
    for (int i = 0; i < 4; i++) {
        int c = tid + i * 256;
        x[i] = a[c] + b[c];
        s += x[i];
        s2 += x[i] * x[i];
    }
#pragma unroll
    for (int off = 16; off; off >>= 1) {
        s  += __shfl_down_sync(0xffffffffu, s,  off);
        s2 += __shfl_down_sync(0xffffffffu, s2, off);
    }
    __shared__ float ss[8], ss2[8];
    __shared__ float s_mean, s_inv;
    int w = tid >> 5;
    if ((tid & 31) == 0) { ss[w] = s; ss2[w] = s2; }
    __syncthreads();
    if (tid == 0) {
        float S = 0.f, S2 = 0.f;
#pragma unroll
        for (int i = 0; i < 8; i++) { S += ss[i]; S2 += ss2[i]; }
        float mu = S * (1.f / DIM);
        float var = S2 * (1.f / DIM) - mu * mu;
        s_mean = mu;
        s_inv = rsqrtf(var + 1e-5f);
    }
    __syncthreads();
    float mu = s_mean, iv = s_inv;
#pragma unroll
    for (int i = 0; i < 4; i++) {
        int c = tid + i * 256;
        out[(size_t)row * DIM + c] = (x[i] - mu) * iv * g[c] + beta[c];
    }
}

// ---------------- host ----------------
extern "C" void kernel_launch(void* const* d_in, const int* in_sizes, int n_in,
                              void* d_out, int out_size)
{
    const float* kq  = (const float*)d_in[0];
    const float* v   = (const float*)d_in[1];
    const float* Wk  = (const float*)d_in[2];
    const float* bk  = (const float*)d_in[3];
    const float* Wq  = (const float*)d_in[4];
    const float* bq  = (const float*)d_in[5];
    const float* Wv  = (const float*)d_in[6];
    const float* bv  = (const float*)d_in[7];
    const float* W1  = (const float*)d_in[8];
    const float* b1  = (const float*)d_in[9];
    const float* W2  = (const float*)d_in[10];
    const float* b2  = (const float*)d_in[11];
    const float* g1  = (const float*)d_in[12];
    const float* be1 = (const float*)d_in[13];
    const float* g2  = (const float*)d_in[14];
    const float* be2 = (const float*)d_in[15];
    float* out = (float*)d_out;

    float *X, *Kb, *Qb, *Vb, *AO, *Hh, *G, *F;
    cudaGetSymbolAddress((void**)&X,  g_X);
    cudaGetSymbolAddress((void**)&Kb, g_K);
    cudaGetSymbolAddress((void**)&Qb, g_Q);
    cudaGetSymbolAddress((void**)&Vb, g_V);
    cudaGetSymbolAddress((void**)&AO, g_AO);
    cudaGetSymbolAddress((void**)&Hh, g_H);
    cudaGetSymbolAddress((void**)&G,  g_G);
    cudaGetSymbolAddress((void**)&F,  g_F);

    concat_kernel<<<(MTOT * DIM) / 256, 256>>>(kq, v);

    dim3 gqkv(DIM / 128, MTOT / 128);
    gemm_mma<0><<<gqkv, 256>>>(X, Wk, bk, Kb, DIM, DIM);
    gemm_mma<0><<<gqkv, 256>>>(X, Wq, bq, Qb, DIM, DIM);
    gemm_mma<0><<<gqkv, 256>>>(X, Wv, bv, Vb, DIM, DIM);

    cudaFuncSetAttribute(attn_mma, cudaFuncAttributeMaxDynamicSharedMemorySize, SMEM_ATTN);
    attn_mma<<<dim3(TT / 64, NHEAD, NBATCH), 128, SMEM_ATTN>>>(Qb, Kb, Vb, AO);

    add_ln_kernel<<<MTOT, 256>>>(Vb, AO, g1, be1, Hh);

    gemm_mma<1><<<dim3(FFD / 128, MTOT / 128), 256>>>(Hh, W1, b1, G, FFD, DIM);
    gemm_mma<0><<<dim3(DIM / 128, MTOT / 128), 256>>>(G, W2, b2, F, DIM, FFD);

    add_ln_kernel<<<MTOT, 256>>>(Hh, F, g2, be2, out);
}

// round 4
// speedup vs baseline: 2.6504x; 1.0939x over previous
#include <cuda_runtime.h>
#include <math.h>

#define MTOT 8192      // n * T = 4 * 2048
#define DIM 1024
#define FFD 4096
#define TT 2048
#define NBATCH 4
#define NHEAD 16
#define HDIM 64

// ---------------- scratch (no allocs allowed) ----------------
__device__ float g_X [MTOT * DIM];   // concat(kq, v)
__device__ float g_K [MTOT * DIM];
__device__ float g_Q [MTOT * DIM];
__device__ float g_V [MTOT * DIM];
__device__ float g_AO[MTOT * DIM];   // attention output
__device__ float g_H [MTOT * DIM];   // after LN1
__device__ float g_G [MTOT * FFD];   // gelu(h W1^T + b1)
__device__ float g_F [MTOT * DIM];   // ffn output

// ---------------- helpers ----------------
__device__ __forceinline__ unsigned cvt_tf32(float f) {
    unsigned r;
    asm("cvt.rna.tf32.f32 %0, %1;" : "=r"(r) : "f"(f));
    return r;
}
__device__ __forceinline__ float tf32f(float f) { return __uint_as_float(cvt_tf32(f)); }

__device__ __forceinline__ void mma8(float* c, const unsigned* a, const unsigned* b) {
    asm volatile(
        "mma.sync.aligned.m16n8k8.row.col.f32.tf32.tf32.f32 "
        "{%0,%1,%2,%3}, {%4,%5,%6,%7}, {%8,%9}, {%0,%1,%2,%3};\n"
        : "+f"(c[0]), "+f"(c[1]), "+f"(c[2]), "+f"(c[3])
        : "r"(a[0]), "r"(a[1]), "r"(a[2]), "r"(a[3]), "r"(b[0]), "r"(b[1]));
}

// ---------------- concat ----------------
__global__ void concat_kernel(const float* __restrict__ kq, const float* __restrict__ v) {
    int i = blockIdx.x * blockDim.x + threadIdx.x;
    int m = i >> 10;
    int j = i & 1023;
    g_X[i] = (j < 512) ? kq[m * 512 + j] : v[m * 512 + (j - 512)];
}

// ---------------- tf32 tensor-core GEMM ----------------
// C[M,N] = A[M,K]*B[N,K]^T + bias (+GELU).
// Block tile 256x128x16, 8 warps (4 M x 2 N), warp tile 64x64, mma.m16n8k8.tf32.
// Quad-packed smem: one float4 per fragment = {(r+g,tg),(r+g,tg+4),(r+g+8,tg),(r+g+8,tg+4)}
// slot index within 8-slot group = (g + 2*tg) & 7  -> conflict-free LDS.128 and STS.64.
// A region: 1024 float4 (2ks x 4tg x 16 mblk x 8), B region: 512 float4 (2ks x 4tg x 8 nblk x 8).
#define GSTG 1536      // float4 per stage (A 1024 + B 512)

template<int GELU>
__global__ void __launch_bounds__(256, 1) gemm_mma(
    const float* __restrict__ A, const float* __restrict__ B,
    const float* __restrict__ bias, float* __restrict__ C,
    int N, int K)
{
    extern __shared__ float4 s4[];   // [2][GSTG]

    const int tid  = threadIdx.x;
    const int lane = tid & 31;
    const int warp = tid >> 5;
    const int g    = lane >> 2;
    const int tg   = lane & 3;
    const int wm   = (warp & 3) * 64;
    const int wn   = (warp >> 2) * 64;
    const int bm   = blockIdx.y * 256;
    const int bn   = blockIdx.x * 128;
    const int sgc  = (g + 2 * tg) & 7;

    // producer mapping: A row = tid (16 k's), B row = tid&127 at kstep tid>>7 (8 k's)
    const int arow = tid;
    const int brow = tid & 127;
    const int bks  = tid >> 7;
    const float* Ap = A + (size_t)(bm + arow) * K;
    const float* Bp = B + (size_t)(bn + brow) * K + bks * 8;

    // precomputed store slots
    const int amb = arow >> 4, ag = arow & 7, ah = (arow >> 3) & 1;
    const int bnb = brow >> 4, bg = brow & 7, bh = (brow >> 3) & 1;

    float acc[4][8][4];
#pragma unroll
    for (int i = 0; i < 4; i++)
#pragma unroll
        for (int j = 0; j < 8; j++)
#pragma unroll
            for (int q = 0; q < 4; q++) acc[i][j][q] = 0.f;

    float ra[16], rb[8];
    {
        float4 t0 = *(const float4*)(Ap +  0);
        float4 t1 = *(const float4*)(Ap +  4);
        float4 t2 = *(const float4*)(Ap +  8);
        float4 t3 = *(const float4*)(Ap + 12);
        ra[0]=t0.x; ra[1]=t0.y; ra[2]=t0.z; ra[3]=t0.w;
        ra[4]=t1.x; ra[5]=t1.y; ra[6]=t1.z; ra[7]=t1.w;
        ra[8]=t2.x; ra[9]=t2.y; ra[10]=t2.z; ra[11]=t2.w;
        ra[12]=t3.x; ra[13]=t3.y; ra[14]=t3.z; ra[15]=t3.w;
        float4 u0 = *(const float4*)(Bp);
        float4 u1 = *(const float4*)(Bp + 4);
        rb[0]=u0.x; rb[1]=u0.y; rb[2]=u0.z; rb[3]=u0.w;
        rb[4]=u1.x; rb[5]=u1.y; rb[6]=u1.z; rb[7]=u1.w;
    }

    // store stage 0
    {
        float2* s2 = (float2*)(s4);
#pragma unroll
        for (int ks = 0; ks < 2; ks++)
#pragma unroll
            for (int p = 0; p < 4; p++) {
                int idx = ks * 512 + p * 128 + amb * 8 + ((ag + 2 * p) & 7);
                s2[idx * 2 + ah] = make_float2(tf32f(ra[ks * 8 + p]), tf32f(ra[ks * 8 + p + 4]));
            }
#pragma unroll
        for (int p = 0; p < 4; p++) {
            int idx = 1024 + bks * 256 + p * 64 + bnb * 8 + ((bg + 2 * p) & 7);
            s2[idx * 2 + bh] = make_float2(tf32f(rb[p]), tf32f(rb[p + 4]));
        }
    }
    __syncthreads();

    int buf = 0;
    for (int k0 = 0; k0 < K; k0 += 16) {
        const bool more = (k0 + 16 < K);
        if (more) {
            const float* ap = Ap + k0 + 16;
            float4 t0 = *(const float4*)(ap +  0);
            float4 t1 = *(const float4*)(ap +  4);
            float4 t2 = *(const float4*)(ap +  8);
            float4 t3 = *(const float4*)(ap + 12);
            ra[0]=t0.x; ra[1]=t0.y; ra[2]=t0.z; ra[3]=t0.w;
            ra[4]=t1.x; ra[5]=t1.y; ra[6]=t1.z; ra[7]=t1.w;
            ra[8]=t2.x; ra[9]=t2.y; ra[10]=t2.z; ra[11]=t2.w;
            ra[12]=t3.x; ra[13]=t3.y; ra[14]=t3.z; ra[15]=t3.w;
            float4 u0 = *(const float4*)(Bp + k0 + 16);
            float4 u1 = *(const float4*)(Bp + k0 + 20);
            rb[0]=u0.x; rb[1]=u0.y; rb[2]=u0.z; rb[3]=u0.w;
            rb[4]=u1.x; rb[5]=u1.y; rb[6]=u1.z; rb[7]=u1.w;
        }

        const float4* sa = s4 + buf * GSTG;
        const float4* sb = sa + 1024;
#pragma unroll
        for (int ks = 0; ks < 2; ks++) {
            unsigned af[4][4], bf[8][2];
#pragma unroll
            for (int mi = 0; mi < 4; mi++) {
                float4 a4 = sa[ks * 512 + tg * 128 + ((wm >> 4) + mi) * 8 + sgc];
                af[mi][0] = __float_as_uint(a4.x);
                af[mi][1] = __float_as_uint(a4.z);
                af[mi][2] = __float_as_uint(a4.y);
                af[mi][3] = __float_as_uint(a4.w);
            }
#pragma unroll
            for (int j = 0; j < 4; j++) {
                float4 b4 = sb[ks * 256 + tg * 64 + ((wn >> 4) + j) * 8 + sgc];
                bf[2 * j][0]     = __float_as_uint(b4.x);
                bf[2 * j][1]     = __float_as_uint(b4.y);
                bf[2 * j + 1][0] = __float_as_uint(b4.z);
                bf[2 * j + 1][1] = __float_as_uint(b4.w);
            }
#pragma unroll
            for (int mi = 0; mi < 4; mi++)
#pragma unroll
                for (int ni = 0; ni < 8; ni++)
                    mma8(acc[mi][ni], af[mi], bf[ni]);
        }

        if (more) {
            float2* s2 = (float2*)(s4 + (buf ^ 1) * GSTG);
#pragma unroll
            for (int ks = 0; ks < 2; ks++)
#pragma unroll
                for (int p = 0; p < 4; p++) {
                    int idx = ks * 512 + p * 128 + amb * 8 + ((ag + 2 * p) & 7);
                    s2[idx * 2 + ah] = make_float2(tf32f(ra[ks * 8 + p]), tf32f(ra[ks * 8 + p + 4]));
                }
#pragma unroll
            for (int p = 0; p < 4; p++) {
                int idx = 1024 + bks * 256 + p * 64 + bnb * 8 + ((bg + 2 * p) & 7);
                s2[idx * 2 + bh] = make_float2(tf32f(rb[p]), tf32f(rb[p + 4]));
            }
        }
        __syncthreads();
        buf ^= 1;
    }

    // epilogue
#pragma unroll
    for (int ni = 0; ni < 8; ni++) {
        int n = bn + wn + ni * 8 + tg * 2;
        float b0 = bias[n], b1 = bias[n + 1];
#pragma unroll
        for (int mi = 0; mi < 4; mi++) {
            int m = bm + wm + mi * 16 + g;
            float v00 = acc[mi][ni][0] + b0;
            float v01 = acc[mi][ni][1] + b1;
            float v10 = acc[mi][ni][2] + b0;
            float v11 = acc[mi][ni][3] + b1;
            if (GELU) {
                v00 = 0.5f * v00 * (1.f + erff(v00 * 0.7071067811865476f));
                v01 = 0.5f * v01 * (1.f + erff(v01 * 0.7071067811865476f));
                v10 = 0.5f * v10 * (1.f + erff(v10 * 0.7071067811865476f));
                v11 = 0.5f * v11 * (1.f + erff(v11 * 0.7071067811865476f));
            }
            *(float2*)&C[(size_t)m * N + n] = make_float2(v00, v01);
            *(float2*)&C[(size_t)(m + 8) * N + n] = make_float2(v10, v11);
        }
    }
}

// ---------------- attention: tf32 mma flash, causal, no scale ----------------
#define QPLN 68           // float2 per plane row (64 + 4 pad)
#define PSTR 72           // P row stride in floats
#define SMEM_ATTN (13312 * 4)

__global__ void __launch_bounds__(128, 3) attn_mma(
    const float* __restrict__ Qg, const float* __restrict__ Kg,
    const float* __restrict__ Vg, float* __restrict__ AO)
{
    extern __shared__ float sm[];
    float2* Kp  = (float2*)sm;
    float*  Vf  = sm + 4352;
    float2* Vp  = (float2*)Vf;
    float2* Qp2 = (float2*)(sm + 8704);
    float*  Ps  = sm + 8704;

    const int qb = blockIdx.x, h = blockIdx.y, b = blockIdx.z;
    const int tid = threadIdx.x;
    const int warp = tid >> 5, lane = tid & 31;
    const int g = lane >> 2, tg = lane & 3;
    const int qw0 = warp * 16;
    const size_t base = ((size_t)b * TT) * DIM + (size_t)h * HDIM;
    const int q0 = qb * 64;

    for (int t = tid; t < 512; t += 128) {
        int row = t & 63, ks = t >> 6;
        const float* src = Qg + base + (size_t)(q0 + row) * DIM + ks * 8;
        float4 v0 = *(const float4*)src, v1 = *(const float4*)(src + 4);
        float a[8] = {v0.x, v0.y, v0.z, v0.w, v1.x, v1.y, v1.z, v1.w};
#pragma unroll
        for (int p = 0; p < 4; p++)
            Qp2[(ks * 4 + p) * QPLN + row] = make_float2(tf32f(a[p]), tf32f(a[p + 4]));
    }
    __syncthreads();

    unsigned qf[8][4];
#pragma unroll
    for (int ks = 0; ks < 8; ks++) {
        float2 lo = Qp2[(ks * 4 + tg) * QPLN + qw0 + g];
        float2 hi = Qp2[(ks * 4 + tg) * QPLN + qw0 + g + 8];
        qf[ks][0] = __float_as_uint(lo.x);
        qf[ks][1] = __float_as_uint(hi.x);
        qf[ks][2] = __float_as_uint(lo.y);
        qf[ks][3] = __float_as_uint(hi.y);
    }

    float o[8][4];
#pragma unroll
    for (int ni = 0; ni < 8; ni++)
#pragma unroll
        for (int q = 0; q < 4; q++) o[ni][q] = 0.f;
    float m0 = -INFINITY, m1 = -INFINITY, l0 = 0.f, l1 = 0.f;

    for (int jb = 0; jb <= qb; jb++) {
        __syncthreads();
        const int k0 = jb * 64;
        for (int t = tid; t < 512; t += 128) {
            int row = t & 63, ks = t >> 6;
            const float* src = Kg + base + (size_t)(k0 + row) * DIM + ks * 8;
            float4 v0 = *(const float4*)src, v1 = *(const float4*)(src + 4);
            float a[8] = {v0.x, v0.y, v0.z, v0.w, v1.x, v1.y, v1.z, v1.w};
#pragma unroll
            for (int p = 0; p < 4; p++)
                Kp[(ks * 4 + p) * QPLN + row] = make_float2(tf32f(a[p]), tf32f(a[p + 4]));
        }
        for (int t = tid; t < 512; t += 128) {
            int row = t & 63, ch = t >> 6;
            const float* src = Vg + base + (size_t)(k0 + row) * DIM + ch * 8;
            float4 v0 = *(const float4*)src, v1 = *(const float4*)(src + 4);
            float a[8] = {v0.x, v0.y, v0.z, v0.w, v1.x, v1.y, v1.z, v1.w};
            int plane = (row >> 3) * 4 + (row & 3);
            int slot = (row & 4) >> 2;
            float* dst = Vf + plane * 136 + slot;
#pragma unroll
            for (int e = 0; e < 8; e++)
                dst[(ch * 8 + e) * 2] = tf32f(a[e]);
        }
        __syncthreads();

        float s[8][4];
#pragma unroll
        for (int ni = 0; ni < 8; ni++)
#pragma unroll
            for (int q = 0; q < 4; q++) s[ni][q] = 0.f;
#pragma unroll
        for (int ks = 0; ks < 8; ks++) {
#pragma unroll
            for (int ni = 0; ni < 8; ni++) {
                float2 kb = Kp[(ks * 4 + tg) * QPLN + ni * 8 + g];
                unsigned bf[2] = {__float_as_uint(kb.x), __float_as_uint(kb.y)};
                mma8(s[ni], qf[ks], bf);
            }
        }

        if (jb == qb) {
#pragma unroll
            for (int ni = 0; ni < 8; ni++) {
                int c = ni * 8 + 2 * tg;
                if (c     > qw0 + g)     s[ni][0] = -INFINITY;
                if (c + 1 > qw0 + g)     s[ni][1] = -INFINITY;
                if (c     > qw0 + g + 8) s[ni][2] = -INFINITY;
                if (c + 1 > qw0 + g + 8) s[ni][3] = -INFINITY;
            }
        }

        float rx0 = -INFINITY, rx1 = -INFINITY;
#pragma unroll
        for (int ni = 0; ni < 8; ni++) {
            rx0 = fmaxf(rx0, fmaxf(s[ni][0], s[ni][1]));
            rx1 = fmaxf(rx1, fmaxf(s[ni][2], s[ni][3]));
        }
        rx0 = fmaxf(rx0, __shfl_xor_sync(0xffffffffu, rx0, 1));
        rx0 = fmaxf(rx0, __shfl_xor_sync(0xffffffffu, rx0, 2));
        rx1 = fmaxf(rx1, __shfl_xor_sync(0xffffffffu, rx1, 1));
        rx1 = fmaxf(rx1, __shfl_xor_sync(0xffffffffu, rx1, 2));

        float mn0 = fmaxf(m0, rx0), mn1 = fmaxf(m1, rx1);
        float al0 = __expf(m0 - mn0), al1 = __expf(m1 - mn1);
        float ps0 = 0.f, ps1 = 0.f;
#pragma unroll
        for (int ni = 0; ni < 8; ni++) {
            float p0 = tf32f(__expf(s[ni][0] - mn0));
            float p1 = tf32f(__expf(s[ni][1] - mn0));
            float p2 = tf32f(__expf(s[ni][2] - mn1));
            float p3 = tf32f(__expf(s[ni][3] - mn1));
            s[ni][0] = p0; s[ni][1] = p1; s[ni][2] = p2; s[ni][3] = p3;
            ps0 += p0 + p1;
            ps1 += p2 + p3;
        }
        ps0 += __shfl_xor_sync(0xffffffffu, ps0, 1);
        ps0 += __shfl_xor_sync(0xffffffffu, ps0, 2);
        ps1 += __shfl_xor_sync(0xffffffffu, ps1, 1);
        ps1 += __shfl_xor_sync(0xffffffffu, ps1, 2);
        l0 = l0 * al0 + ps0;
        l1 = l1 * al1 + ps1;
        m0 = mn0; m1 = mn1;
#pragma unroll
        for (int ni = 0; ni < 8; ni++) {
            o[ni][0] *= al0; o[ni][1] *= al0;
            o[ni][2] *= al1; o[ni][3] *= al1;
        }

#pragma unroll
        for (int ni = 0; ni < 8; ni++) {
            *(float2*)&Ps[(qw0 + g)     * PSTR + ni * 8 + 2 * tg] = make_float2(s[ni][0], s[ni][1]);
            *(float2*)&Ps[(qw0 + g + 8) * PSTR + ni * 8 + 2 * tg] = make_float2(s[ni][2], s[ni][3]);
        }
        __syncwarp();

#pragma unroll
        for (int ks = 0; ks < 8; ks++) {
            unsigned pf[4];
            pf[0] = __float_as_uint(Ps[(qw0 + g)     * PSTR + ks * 8 + tg]);
            pf[1] = __float_as_uint(Ps[(qw0 + g + 8) * PSTR + ks * 8 + tg]);
            pf[2] = __float_as_uint(Ps[(qw0 + g)     * PSTR + ks * 8 + tg + 4]);
            pf[3] = __float_as_uint(Ps[(qw0 + g + 8) * PSTR + ks * 8 + tg + 4]);
#pragma unroll
            for (int ni = 0; ni < 8; ni++) {
                float2 vb = Vp[(ks * 4 + tg) * QPLN + ni * 8 + g];
                unsigned bf[2] = {__float_as_uint(vb.x), __float_as_uint(vb.y)};
                mma8(o[ni], pf, bf);
            }
        }
    }

    float i0 = 1.f / l0, i1 = 1.f / l1;
#pragma unroll
    for (int ni = 0; ni < 8; ni++) {
        size_t r0 = base + (size_t)(q0 + qw0 + g) * DIM + ni * 8 + 2 * tg;
        size_t r1 = base + (size_t)(q0 + qw0 + g + 8) * DIM + ni * 8 + 2 * tg;
        *(float2*)&AO[r0] = make_float2(o[ni][0] * i0, o[ni][1] * i0);
        *(float2*)&AO[r1] = make_float2(o[ni][2] * i1, o[ni][3] * i1);
    }
}

// ---------------- fused add + LayerNorm (row = 1024) ----------------
__global__ void __launch_bounds__(256) add_ln_kernel(
    const float* __restrict__ A, const float* __restrict__ B,
    const float* __restrict__ g, const float* __restrict__ beta,
    float* __restrict__ out)
{
    const int row = blockIdx.x;
    const float* a = A + (size_t)row * DIM;
    const float* b = B + (size_t)row * DIM;
    const int tid = threadIdx.x;

    float x[4];
    float s = 0.f, s2 = 0.f;
#pragma unroll
    for (int i = 0; i < 4; i++) {
        int c = tid + i * 256;
        x[i] = a[c] + b[c];
        s += x[i];
        s2 += x[i] * x[i];
    }
#pragma unroll
    for (int off = 16; off; off >>= 1) {
        s  += __shfl_down_sync(0xffffffffu, s,  off);
        s2 += __shfl_down_sync(0xffffffffu, s2, off);
    }
    __shared__ float ss[8], ss2[8];
    __shared__ float s_mean, s_inv;
    int w = tid >> 5;
    if ((tid & 31) == 0) { ss[w] = s; ss2[w] = s2; }
    __syncthreads();
    if (tid == 0) {
        float S = 0.f, S2 = 0.f;
#pragma unroll
        for (int i = 0; i < 8; i++) { S += ss[i]; S2 += ss2[i]; }
        float mu = S * (1.f / DIM);
        float var = S2 * (1.f / DIM) - mu * mu;
        s_mean = mu;
        s_inv = rsqrtf(var + 1e-5f);
    }
    __syncthreads();
    float mu = s_mean, iv = s_inv;
#pragma unroll
    for (int i = 0; i < 4; i++) {
        int c = tid + i * 256;
        out[(size_t)row * DIM + c] = (x[i] - mu) * iv * g[c] + beta[c];
    }
}

// ---------------- host ----------------
extern "C" void kernel_launch(void* const* d_in, const int* in_sizes, int n_in,
                              void* d_out, int out_size)
{
    const float* kq  = (const float*)d_in[0];
    const float* v   = (const float*)d_in[1];
    const float* Wk  = (const float*)d_in[2];
    const float* bk  = (const float*)d_in[3];
    const float* Wq  = (const float*)d_in[4];
    const float* bq  = (const float*)d_in[5];
    const float* Wv  = (const float*)d_in[6];
    const float* bv  = (const float*)d_in[7];
    const float* W1  = (const float*)d_in[8];
    const float* b1  = (const float*)d_in[9];
    const float* W2  = (const float*)d_in[10];
    const float* b2  = (const float*)d_in[11];
    const float* g1  = (const float*)d_in[12];
    const float* be1 = (const float*)d_in[13];
    const float* g2  = (const float*)d_in[14];
    const float* be2 = (const float*)d_in[15];
    float* out = (float*)d_out;

    float *X, *Kb, *Qb, *Vb, *AO, *Hh, *G, *F;
    cudaGetSymbolAddress((void**)&X,  g_X);
    cudaGetSymbolAddress((void**)&Kb, g_K);
    cudaGetSymbolAddress((void**)&Qb, g_Q);
    cudaGetSymbolAddress((void**)&Vb, g_V);
    cudaGetSymbolAddress((void**)&AO, g_AO);
    cudaGetSymbolAddress((void**)&Hh, g_H);
    cudaGetSymbolAddress((void**)&G,  g_G);
    cudaGetSymbolAddress((void**)&F,  g_F);

    const int GSMEM = 2 * GSTG * 16;   // 49152 bytes
    cudaFuncSetAttribute(gemm_mma<0>, cudaFuncAttributeMaxDynamicSharedMemorySize, GSMEM);
    cudaFuncSetAttribute(gemm_mma<1>, cudaFuncAttributeMaxDynamicSharedMemorySize, GSMEM);

    concat_kernel<<<(MTOT * DIM) / 256, 256>>>(kq, v);

    dim3 gqkv(DIM / 128, MTOT / 256);
    gemm_mma<0><<<gqkv, 256, GSMEM>>>(X, Wk, bk, Kb, DIM, DIM);
    gemm_mma<0><<<gqkv, 256, GSMEM>>>(X, Wq, bq, Qb, DIM, DIM);
    gemm_mma<0><<<gqkv, 256, GSMEM>>>(X, Wv, bv, Vb, DIM, DIM);

    cudaFuncSetAttribute(attn_mma, cudaFuncAttributeMaxDynamicSharedMemorySize, SMEM_ATTN);
    attn_mma<<<dim3(TT / 64, NHEAD, NBATCH), 128, SMEM_ATTN>>>(Qb, Kb, Vb, AO);

    add_ln_kernel<<<MTOT, 256>>>(Vb, AO, g1, be1, Hh);

    gemm_mma<1><<<dim3(FFD / 128, MTOT / 256), 256, GSMEM>>>(Hh, W1, b1, G, FFD, DIM);
    gemm_mma<0><<<dim3(DIM / 128, MTOT / 256), 256, GSMEM>>>(G, W2, b2, F, DIM, FFD);

    add_ln_kernel<<<MTOT, 256>>>(Hh, F, g2, be2, out);
}